// round 6
// baseline (speedup 1.0000x reference)
#include <cuda_runtime.h>
#include <cuda_bf16.h>
#include <cstdint>

// Problem constants
#define B_   2
#define S_   4096
#define D_   512
#define H_   8
#define DK_  64
#define BH_  (B_*H_)
#define M_   (B_*S_)   // 8192 rows

// score scale folded into Q: 1/sqrt(64) * log2(e)  (softmax done in exp2 domain)
#define QSCALE (0.125f * 1.44269504088896341f)

// ---------------- scratch (no allocations allowed -> device globals) ----------
__device__ float g_Qh[BH_ * S_ * DK_];   // [bh][s][dk]  16 MiB
__device__ float g_Kh[BH_ * S_ * DK_];
__device__ float g_Vh[BH_ * S_ * DK_];
__device__ float g_cmax[BH_ * S_];       // per-column (k) max over q (log2 domain)
__device__ float g_csum[BH_ * S_];       // per-column (k) sum of exp2
__device__ float g_attn[M_ * D_];        // [b*S+s][h*64+dv]

// ---------------- tf32 helpers (attention core) -------------------------------
__device__ __forceinline__ float to_tf32(float x) {
    uint32_t u;
    asm("cvt.rna.tf32.f32 %0, %1;" : "=r"(u) : "f"(x));
    return __uint_as_float(u);
}

// D += A(16x8,row) * B(8x8,col)  tf32, fp32 accum
__device__ __forceinline__ void mma8(float* c,
                                     uint32_t a0, uint32_t a1, uint32_t a2, uint32_t a3,
                                     uint32_t b0, uint32_t b1) {
    asm volatile(
        "mma.sync.aligned.m16n8k8.row.col.f32.tf32.tf32.f32 "
        "{%0,%1,%2,%3}, {%4,%5,%6,%7}, {%8,%9}, {%0,%1,%2,%3};\n"
        : "+f"(c[0]), "+f"(c[1]), "+f"(c[2]), "+f"(c[3])
        : "r"(a0), "r"(a1), "r"(a2), "r"(a3), "r"(b0), "r"(b1));
}

// ---------------- bf16 helpers (dense GEMMs, split precision) -----------------
// D += A(16x16,row) * B(16x8,col)  bf16, fp32 accum
__device__ __forceinline__ void mma16(float* c,
                                      uint32_t a0, uint32_t a1, uint32_t a2, uint32_t a3,
                                      uint32_t b0, uint32_t b1) {
    asm volatile(
        "mma.sync.aligned.m16n8k16.row.col.f32.bf16.bf16.f32 "
        "{%0,%1,%2,%3}, {%4,%5,%6,%7}, {%8,%9}, {%0,%1,%2,%3};\n"
        : "+f"(c[0]), "+f"(c[1]), "+f"(c[2]), "+f"(c[3])
        : "r"(a0), "r"(a1), "r"(a2), "r"(a3), "r"(b0), "r"(b1));
}

__device__ __forceinline__ uint32_t pack_bf2(__nv_bfloat16 lo, __nv_bfloat16 hi) {
    __nv_bfloat162 t(lo, hi);               // .x = lo (low 16 bits)
    return *reinterpret_cast<uint32_t*>(&t);
}

// split x into big(bf16) + small(bf16 of residual)
__device__ __forceinline__ void split_bf16(float x, __nv_bfloat16& b, __nv_bfloat16& s) {
    b = __float2bfloat16_rn(x);
    s = __float2bfloat16_rn(x - __bfloat162float(b));
}

// =============================================================================
// Dense GEMM core (bf16 split, 3-mma).  Block tile 128m x 128n, K=512,
// k-chunk 16.  8 warps as 4m x 2n -> warp tile 32m x 64n.
// Smem rows stride 12 u32 (k/2 pairs + pad) -> conflict-free fragment LDS.
// Software pipeline: LDG of chunk kc+16 issued right after STS of chunk kc.
// =============================================================================
#define GEMM_BODY(A_EXPR, W_EXPR)                                                \
    __shared__ uint32_t AuB[128 * 12], AuS[128 * 12];                            \
    __shared__ uint32_t BuB[128 * 12], BuS[128 * 12];                            \
    const int tid = threadIdx.x;                                                 \
    const int warp = tid >> 5, lane = tid & 31;                                  \
    const int gid = lane >> 2, tig = lane & 3;                                   \
    const int m0w = (warp & 3) * 32;                                             \
    const int n0w = (warp >> 2) * 64;                                            \
    const int m0 = blockIdx.x * 128;                                             \
    const int n0 = blockIdx.y * 128;                                             \
    float c[2][8][4];                                                            \
    _Pragma("unroll") for (int mb = 0; mb < 2; mb++)                             \
    _Pragma("unroll") for (int nb = 0; nb < 8; nb++)                             \
    _Pragma("unroll") for (int j = 0; j < 4; j++) c[mb][nb][j] = 0.f;            \
    const int ar = tid >> 1;                                                     \
    const int ac = (tid & 1) * 8;                                                \
    const int kp = tid >> 5;                                                     \
    const int ln = tid & 31;                                                     \
    float4 pA0, pA1;                                                             \
    float pBv[8];                                                                \
    {                                                                            \
        const float* ap = &(A_EXPR)[(size_t)(m0 + ar) * D_ + ac];                \
        pA0 = *(const float4*)ap; pA1 = *(const float4*)(ap + 4);                \
        _Pragma("unroll") for (int p = 0; p < 4; p++) {                          \
            int n = ln + p * 32;                                                 \
            pBv[2*p]   = (W_EXPR)[(size_t)(2*kp    ) * D_ + n0 + n];             \
            pBv[2*p+1] = (W_EXPR)[(size_t)(2*kp + 1) * D_ + n0 + n];             \
        }                                                                        \
    }                                                                            \
    for (int kc = 0; kc < 512; kc += 16) {                                       \
        __syncthreads();                                                         \
        { /* store A chunk (bf16 split, k-pairs packed) */                       \
            __nv_bfloat16 b0,s0,b1,s1,b2,s2,b3,s3;                               \
            split_bf16(pA0.x,b0,s0); split_bf16(pA0.y,b1,s1);                    \
            split_bf16(pA0.z,b2,s2); split_bf16(pA0.w,b3,s3);                    \
            AuB[ar*12 + ac/2 + 0] = pack_bf2(b0,b1);                             \
            AuS[ar*12 + ac/2 + 0] = pack_bf2(s0,s1);                             \
            AuB[ar*12 + ac/2 + 1] = pack_bf2(b2,b3);                             \
            AuS[ar*12 + ac/2 + 1] = pack_bf2(s2,s3);                             \
            split_bf16(pA1.x,b0,s0); split_bf16(pA1.y,b1,s1);                    \
            split_bf16(pA1.z,b2,s2); split_bf16(pA1.w,b3,s3);                    \
            AuB[ar*12 + ac/2 + 2] = pack_bf2(b0,b1);                             \
            AuS[ar*12 + ac/2 + 2] = pack_bf2(s0,s1);                             \
            AuB[ar*12 + ac/2 + 3] = pack_bf2(b2,b3);                             \
            AuS[ar*12 + ac/2 + 3] = pack_bf2(s2,s3);                             \
        }                                                                        \
        { /* store B chunk: Bu[n][k/2] (transposed+packed) */                    \
            _Pragma("unroll") for (int p = 0; p < 4; p++) {                      \
                int n = ln + p * 32;                                             \
                __nv_bfloat16 xb0,xs0,xb1,xs1;                                   \
                split_bf16(pBv[2*p],xb0,xs0); split_bf16(pBv[2*p+1],xb1,xs1);    \
                BuB[n*12 + kp] = pack_bf2(xb0,xb1);                              \
                BuS[n*12 + kp] = pack_bf2(xs0,xs1);                              \
            }                                                                    \
        }                                                                        \
        if (kc + 16 < 512) { /* prefetch next chunk */                           \
            const float* ap = &(A_EXPR)[(size_t)(m0 + ar) * D_ + kc + 16 + ac];  \
            pA0 = *(const float4*)ap; pA1 = *(const float4*)(ap + 4);            \
            _Pragma("unroll") for (int p = 0; p < 4; p++) {                      \
                int n = ln + p * 32;                                             \
                pBv[2*p]   = (W_EXPR)[(size_t)(kc + 16 + 2*kp    ) * D_ + n0 + n]; \
                pBv[2*p+1] = (W_EXPR)[(size_t)(kc + 16 + 2*kp + 1) * D_ + n0 + n]; \
            }                                                                    \
        }                                                                        \
        __syncthreads();                                                         \
        uint32_t a_b[2][4], a_s[2][4];                                           \
        _Pragma("unroll") for (int mb = 0; mb < 2; mb++) {                       \
            int base = (m0w + mb * 16) * 12;                                     \
            a_b[mb][0] = AuB[base + gid*12 + tig];                               \
            a_b[mb][1] = AuB[base + (gid+8)*12 + tig];                           \
            a_b[mb][2] = AuB[base + gid*12 + tig + 4];                           \
            a_b[mb][3] = AuB[base + (gid+8)*12 + tig + 4];                       \
            a_s[mb][0] = AuS[base + gid*12 + tig];                               \
            a_s[mb][1] = AuS[base + (gid+8)*12 + tig];                           \
            a_s[mb][2] = AuS[base + gid*12 + tig + 4];                           \
            a_s[mb][3] = AuS[base + (gid+8)*12 + tig + 4];                       \
        }                                                                        \
        _Pragma("unroll") for (int nb = 0; nb < 8; nb++) {                       \
            int br = (n0w + nb * 8 + gid) * 12;                                  \
            uint32_t bb0 = BuB[br + tig], bb1 = BuB[br + tig + 4];               \
            uint32_t bs0 = BuS[br + tig], bs1 = BuS[br + tig + 4];               \
            _Pragma("unroll") for (int mb = 0; mb < 2; mb++) {                   \
                mma16(c[mb][nb], a_b[mb][0],a_b[mb][1],a_b[mb][2],a_b[mb][3], bs0,bs1); \
                mma16(c[mb][nb], a_s[mb][0],a_s[mb][1],a_s[mb][2],a_s[mb][3], bb0,bb1); \
                mma16(c[mb][nb], a_b[mb][0],a_b[mb][1],a_b[mb][2],a_b[mb][3], bb0,bb1); \
            }                                                                    \
        }                                                                        \
    }

// ---- fused QKV projections: blockIdx.z selects {q,k,v} -----------------------
struct QKVArgs {
    const float* A[3];
    const float* W[3];
    const float* bias[3];
    float*       out[3];
};

__global__ __launch_bounds__(256) void qkv_gemm(QKVArgs args)
{
    const float* Ain  = args.A[blockIdx.z];
    const float* W    = args.W[blockIdx.z];
    const float* bias = args.bias[blockIdx.z];
    float*       outp = args.out[blockIdx.z];

    GEMM_BODY(Ain, W)

    const int b = m0 >> 12;            // / S_ (128 | 4096 -> one batch per tile)
#pragma unroll
    for (int mb = 0; mb < 2; mb++)
#pragma unroll
        for (int nb = 0; nb < 8; nb++) {
            int row = m0 + m0w + mb * 16 + gid;
            int s = row - b * S_;
            int ng = n0 + n0w + nb * 8 + tig * 2;
            int h = ng >> 6, dk = ng & 63;
            float bx = bias[ng], by = bias[ng + 1];
            float* dst = &outp[((size_t)(b * H_ + h) * S_ + s) * 64 + dk];
            *(float2*)dst = make_float2(c[mb][nb][0] + bx, c[mb][nb][1] + by);
            *(float2*)(dst + 8 * 64) = make_float2(c[mb][nb][2] + bx, c[mb][nb][3] + by);
        }
}

// GEMM 4: final projection g_attn[M,512] @ Wo + bo -> d_out
__global__ __launch_bounds__(256) void out_gemm(const float* __restrict__ W,
                                                const float* __restrict__ bias,
                                                float* __restrict__ out)
{
    GEMM_BODY(g_attn, W)
#pragma unroll
    for (int mb = 0; mb < 2; mb++)
#pragma unroll
        for (int nb = 0; nb < 8; nb++) {
            int row = m0 + m0w + mb * 16 + gid;
            int ng = n0 + n0w + nb * 8 + tig * 2;
            float bx = bias[ng], by = bias[ng + 1];
            *(float2*)&out[(size_t)row * D_ + ng] =
                make_float2(c[mb][nb][0] + bx, c[mb][nb][1] + by);
            *(float2*)&out[(size_t)(row + 8) * D_ + ng] =
                make_float2(c[mb][nb][2] + bx, c[mb][nb][3] + by);
        }
}

// =============================================================================
// Kernel 2 (tf32 mma): column stats over 128-wide k tile; streams 64-q tiles
// with register-prefetch pipeline.  Warp w: q-strip 16*(w&3), k-half 64*(w>>2).
// Q is pre-scaled by QSCALE at load -> scores live in log2 domain; stats use
// exp2.  Both passes apply the identical transform -> bitwise-consistent.
// =============================================================================
#define STATS_SMEM (((128 + 64) * 68 + 4 * 128 + 2 * 128) * 4)

__global__ __launch_bounds__(256) void stats_kernel()
{
    extern __shared__ float sms[];
    float (*Kt)[68] = (float(*)[68])(sms);               // [k][d] 128 rows
    float (*Qt)[68] = (float(*)[68])(sms + 128 * 68);    // [q][d] 64 rows
    float (*red)[128] = (float(*)[128])(sms + 192 * 68);
    float* mcol = sms + 192 * 68 + 4 * 128;
    float* zcol = mcol + 128;

    const int tid = threadIdx.x;
    const int warp = tid >> 5, lane = tid & 31;
    const int gid = lane >> 2, tig = lane & 3;
    const int qw = warp & 3;
    const int q0w = qw * 16;
    const int n0w = (warp >> 2) * 64;

    const int bh = blockIdx.y;
    const int k0 = blockIdx.x * 128;
    const float* Kb = g_Kh + (size_t)bh * S_ * DK_;
    const float* Qb = g_Qh + (size_t)bh * S_ * DK_;

    const int lr = tid >> 2;           // row 0..63
    const int lcb = (tid & 3) * 16;    // col base

    // K tile once (128 rows), row-major, tf32-rounded
#pragma unroll
    for (int half = 0; half < 2; half++) {
        int r = half * 64 + lr;
#pragma unroll
        for (int u = 0; u < 4; u++) {
            float4 t = *(const float4*)&Kb[(size_t)(k0 + r) * DK_ + lcb + u * 4];
            float4 o;
            o.x = to_tf32(t.x); o.y = to_tf32(t.y); o.z = to_tf32(t.z); o.w = to_tf32(t.w);
            *(float4*)&Kt[r][lcb + u * 4] = o;
        }
    }
    if (tid < 128) { mcol[tid] = -1e30f; zcol[tid] = 0.f; }

    // prefetch first Q tile
    float4 pQ[4];
#pragma unroll
    for (int u = 0; u < 4; u++)
        pQ[u] = *(const float4*)&Qb[(size_t)lr * DK_ + lcb + u * 4];

    for (int q0 = 0; q0 < S_; q0 += 64) {
        __syncthreads();
#pragma unroll
        for (int u = 0; u < 4; u++) {
            float4 o;
            o.x = to_tf32(pQ[u].x * QSCALE); o.y = to_tf32(pQ[u].y * QSCALE);
            o.z = to_tf32(pQ[u].z * QSCALE); o.w = to_tf32(pQ[u].w * QSCALE);
            *(float4*)&Qt[lr][lcb + u * 4] = o;
        }
        if (q0 + 64 < S_) {
#pragma unroll
            for (int u = 0; u < 4; u++)
                pQ[u] = *(const float4*)&Qb[(size_t)(q0 + 64 + lr) * DK_ + lcb + u * 4];
        }
        __syncthreads();

        float sc[8][4];
#pragma unroll
        for (int nb = 0; nb < 8; nb++)
#pragma unroll
            for (int j = 0; j < 4; j++) sc[nb][j] = 0.f;

#pragma unroll
        for (int kk = 0; kk < 64; kk += 8) {
            uint32_t a0 = __float_as_uint(Qt[q0w + gid][kk + tig]);
            uint32_t a1 = __float_as_uint(Qt[q0w + gid + 8][kk + tig]);
            uint32_t a2 = __float_as_uint(Qt[q0w + gid][kk + tig + 4]);
            uint32_t a3 = __float_as_uint(Qt[q0w + gid + 8][kk + tig + 4]);
#pragma unroll
            for (int nb = 0; nb < 8; nb++) {
                uint32_t b0 = __float_as_uint(Kt[n0w + nb * 8 + gid][kk + tig]);
                uint32_t b1 = __float_as_uint(Kt[n0w + nb * 8 + gid][kk + tig + 4]);
                mma8(sc[nb], a0, a1, a2, a3, b0, b1);
            }
        }

        // column (k) max over this warp's 16 q rows
#pragma unroll
        for (int nb = 0; nb < 8; nb++) {
            float me = fmaxf(sc[nb][0], sc[nb][2]);
            float mo = fmaxf(sc[nb][1], sc[nb][3]);
#pragma unroll
            for (int off = 4; off <= 16; off <<= 1) {
                me = fmaxf(me, __shfl_xor_sync(0xffffffffu, me, off));
                mo = fmaxf(mo, __shfl_xor_sync(0xffffffffu, mo, off));
            }
            if (gid == 0) {
                int col = n0w + nb * 8 + tig * 2;
                red[qw][col]     = me;
                red[qw][col + 1] = mo;
            }
        }
        __syncthreads();
        if (tid < 128) {
            float t = fmaxf(fmaxf(red[0][tid], red[1][tid]),
                            fmaxf(red[2][tid], red[3][tid]));
            float mo = mcol[tid];
            float mn = fmaxf(mo, t);
            zcol[tid] *= exp2f(mo - mn);   // first tile: 0 * 0 = 0
            mcol[tid] = mn;
        }
        __syncthreads();

        // column sum of exp2 with updated max
#pragma unroll
        for (int nb = 0; nb < 8; nb++) {
            int col = n0w + nb * 8 + tig * 2;
            float m0 = mcol[col], m1 = mcol[col + 1];
            float se = exp2f(sc[nb][0] - m0) + exp2f(sc[nb][2] - m0);
            float so = exp2f(sc[nb][1] - m1) + exp2f(sc[nb][3] - m1);
#pragma unroll
            for (int off = 4; off <= 16; off <<= 1) {
                se += __shfl_xor_sync(0xffffffffu, se, off);
                so += __shfl_xor_sync(0xffffffffu, so, off);
            }
            if (gid == 0) {
                red[qw][col]     = se;
                red[qw][col + 1] = so;
            }
        }
        __syncthreads();
        if (tid < 128)
            zcol[tid] += red[0][tid] + red[1][tid] + red[2][tid] + red[3][tid];
    }
    __syncthreads();
    if (tid < 128) {
        g_cmax[bh * S_ + k0 + tid] = mcol[tid];
        g_csum[bh * S_ + k0 + tid] = zcol[tid];
    }
}

// =============================================================================
// Kernel 3 (tf32 mma): output pass.  Block owns a 128-q tile x DV=64; streams
// 64-k tiles with register-prefetch pipeline: recompute scores (log2 domain),
// p = exp2(s - m_k)/Z_k, acc += P @ V.  Warp w owns q rows [16w, 16w+16).
// Ps is warp-private (produced and consumed by the same warp) -> __syncwarp.
// =============================================================================
#define QT_  128
#define ATT_SMEM (((QT_ + 64 + 64 + QT_) * 68 + 128) * 4)

__global__ __launch_bounds__(256) void attn_kernel()
{
    extern __shared__ float sm[];
    float (*Qt)[68] = (float(*)[68])(sm);                      // [q][d]  128 rows
    float (*Kt)[68] = (float(*)[68])(sm + QT_ * 68);           // [k][d]  64 rows
    float (*Vs)[68] = (float(*)[68])(sm + (QT_ + 64) * 68);    // [d][k]  64 rows (V^T)
    float (*Ps)[68] = (float(*)[68])(sm + (QT_ + 128) * 68);   // [q][k]  128 rows
    float* mk = sm + (2 * QT_ + 128) * 68;
    float* zk = mk + 64;

    const int tid = threadIdx.x;
    const int warp = tid >> 5, lane = tid & 31;
    const int gid = lane >> 2, tig = lane & 3;
    const int q0w = warp * 16;

    const int bh = blockIdx.y;
    const int q0 = blockIdx.x * QT_;
    const int b = bh >> 3, h = bh & 7;
    const float* Qb = g_Qh + (size_t)bh * S_ * DK_;
    const float* Kb = g_Kh + (size_t)bh * S_ * DK_;
    const float* Vb = g_Vh + (size_t)bh * S_ * DK_;

    const int lr = tid >> 2;            // 0..63
    const int lcb = (tid & 3) * 16;

    // Q tile once (row-major, QSCALE + tf32 rounding identical to stats pass)
#pragma unroll
    for (int half = 0; half < 2; half++) {
        int r = half * 64 + lr;
#pragma unroll
        for (int u = 0; u < 4; u++) {
            float4 t = *(const float4*)&Qb[(size_t)(q0 + r) * DK_ + lcb + u * 4];
            float4 o;
            o.x = to_tf32(t.x * QSCALE); o.y = to_tf32(t.y * QSCALE);
            o.z = to_tf32(t.z * QSCALE); o.w = to_tf32(t.w * QSCALE);
            *(float4*)&Qt[r][lcb + u * 4] = o;
        }
    }

    float acc[8][4];
#pragma unroll
    for (int nb = 0; nb < 8; nb++)
#pragma unroll
        for (int j = 0; j < 4; j++) acc[nb][j] = 0.f;

    // prefetch first K/V tile + stats
    float4 pK[4], pV[4];
    float pm = 0.f, pz = 1.f;
#pragma unroll
    for (int u = 0; u < 4; u++) {
        pK[u] = *(const float4*)&Kb[(size_t)lr * DK_ + lcb + u * 4];
        pV[u] = *(const float4*)&Vb[(size_t)lr * DK_ + lcb + u * 4];
    }
    if (tid < 64) { pm = g_cmax[bh * S_ + tid]; pz = g_csum[bh * S_ + tid]; }

    for (int k0 = 0; k0 < S_; k0 += 64) {
        __syncthreads();   // guard Kt/Vs/mk/zk reuse
#pragma unroll
        for (int u = 0; u < 4; u++) {
            float4 o;
            o.x = to_tf32(pK[u].x); o.y = to_tf32(pK[u].y);
            o.z = to_tf32(pK[u].z); o.w = to_tf32(pK[u].w);
            *(float4*)&Kt[lr][lcb + u * 4] = o;
            Vs[lcb + u * 4 + 0][lr] = pV[u].x;   // transpose: [d][k]
            Vs[lcb + u * 4 + 1][lr] = pV[u].y;
            Vs[lcb + u * 4 + 2][lr] = pV[u].z;
            Vs[lcb + u * 4 + 3][lr] = pV[u].w;
        }
        if (tid < 64) { mk[tid] = pm; zk[tid] = 1.f / pz; }
        if (k0 + 64 < S_) {   // prefetch next tile
#pragma unroll
            for (int u = 0; u < 4; u++) {
                pK[u] = *(const float4*)&Kb[(size_t)(k0 + 64 + lr) * DK_ + lcb + u * 4];
                pV[u] = *(const float4*)&Vb[(size_t)(k0 + 64 + lr) * DK_ + lcb + u * 4];
            }
            if (tid < 64) {
                pm = g_cmax[bh * S_ + k0 + 64 + tid];
                pz = g_csum[bh * S_ + k0 + 64 + tid];
            }
        }
        __syncthreads();

        // scores: 16q x 64k per warp (log2 domain)
        float sc[8][4];
#pragma unroll
        for (int nb = 0; nb < 8; nb++)
#pragma unroll
            for (int j = 0; j < 4; j++) sc[nb][j] = 0.f;

#pragma unroll
        for (int kk = 0; kk < 64; kk += 8) {
            uint32_t a0 = __float_as_uint(Qt[q0w + gid][kk + tig]);
            uint32_t a1 = __float_as_uint(Qt[q0w + gid + 8][kk + tig]);
            uint32_t a2 = __float_as_uint(Qt[q0w + gid][kk + tig + 4]);
            uint32_t a3 = __float_as_uint(Qt[q0w + gid + 8][kk + tig + 4]);
#pragma unroll
            for (int nb = 0; nb < 8; nb++) {
                uint32_t b0 = __float_as_uint(Kt[nb * 8 + gid][kk + tig]);
                uint32_t b1 = __float_as_uint(Kt[nb * 8 + gid][kk + tig + 4]);
                mma8(sc[nb], a0, a1, a2, a3, b0, b1);
            }
        }

        // p = exp2(s - m_k) / Z_k, write warp-private P tile
#pragma unroll
        for (int nb = 0; nb < 8; nb++) {
            int col = nb * 8 + tig * 2;
            float m0 = mk[col], z0 = zk[col];
            float m1 = mk[col + 1], z1 = zk[col + 1];
            float p0 = exp2f(sc[nb][0] - m0) * z0;
            float p1 = exp2f(sc[nb][1] - m1) * z1;
            float p2 = exp2f(sc[nb][2] - m0) * z0;
            float p3 = exp2f(sc[nb][3] - m1) * z1;
            *(float2*)&Ps[q0w + gid][col]     = make_float2(p0, p1);
            *(float2*)&Ps[q0w + gid + 8][col] = make_float2(p2, p3);
        }
        __syncwarp();   // Ps rows [q0w, q0w+16) are produced+consumed by this warp only

        // acc += P @ V   (A from Ps[q][k], B from Vs[d][k])
#pragma unroll
        for (int kk = 0; kk < 64; kk += 8) {
            uint32_t a0 = __float_as_uint(Ps[q0w + gid][kk + tig]);
            uint32_t a1 = __float_as_uint(Ps[q0w + gid + 8][kk + tig]);
            uint32_t a2 = __float_as_uint(Ps[q0w + gid][kk + tig + 4]);
            uint32_t a3 = __float_as_uint(Ps[q0w + gid + 8][kk + tig + 4]);
#pragma unroll
            for (int nb = 0; nb < 8; nb++) {
                uint32_t b0 = __float_as_uint(Vs[nb * 8 + gid][kk + tig]);
                uint32_t b1 = __float_as_uint(Vs[nb * 8 + gid][kk + tig + 4]);
                mma8(acc[nb], a0, a1, a2, a3, b0, b1);
            }
        }
    }

    // epilogue: scatter to [b*S+q][h*64+d]
#pragma unroll
    for (int nb = 0; nb < 8; nb++) {
        int col = nb * 8 + tig * 2;
        int q = q0 + q0w + gid;
        *(float2*)&g_attn[((size_t)b * S_ + q) * D_ + h * 64 + col] =
            make_float2(acc[nb][0], acc[nb][1]);
        *(float2*)&g_attn[((size_t)b * S_ + q + 8) * D_ + h * 64 + col] =
            make_float2(acc[nb][2], acc[nb][3]);
    }
}

// =============================================================================
extern "C" void kernel_launch(void* const* d_in, const int* in_sizes, int n_in,
                              void* d_out, int out_size)
{
    const float* q  = (const float*)d_in[0];
    const float* k  = (const float*)d_in[1];
    const float* v  = (const float*)d_in[2];
    const float* Wq = (const float*)d_in[3];
    const float* bq = (const float*)d_in[4];
    const float* Wk = (const float*)d_in[5];
    const float* bk = (const float*)d_in[6];
    const float* Wv = (const float*)d_in[7];
    const float* bv = (const float*)d_in[8];
    const float* Wo = (const float*)d_in[9];
    const float* bo = (const float*)d_in[10];
    float* out = (float*)d_out;

    cudaFuncSetAttribute(attn_kernel, cudaFuncAttributeMaxDynamicSharedMemorySize,
                         ATT_SMEM);
    cudaFuncSetAttribute(stats_kernel, cudaFuncAttributeMaxDynamicSharedMemorySize,
                         STATS_SMEM);

    float* Qh;  cudaGetSymbolAddress((void**)&Qh, g_Qh);
    float* Kh;  cudaGetSymbolAddress((void**)&Kh, g_Kh);
    float* Vh;  cudaGetSymbolAddress((void**)&Vh, g_Vh);

    QKVArgs qa;
    qa.A[0] = q;  qa.A[1] = k;  qa.A[2] = v;
    qa.W[0] = Wq; qa.W[1] = Wk; qa.W[2] = Wv;
    qa.bias[0] = bq; qa.bias[1] = bk; qa.bias[2] = bv;
    qa.out[0] = Qh; qa.out[1] = Kh; qa.out[2] = Vh;

    dim3 blk(256);
    qkv_gemm<<<dim3(M_ / 128, D_ / 128, 3), blk>>>(qa);
    stats_kernel<<<dim3(S_ / 128, BH_), blk, STATS_SMEM>>>();
    attn_kernel<<<dim3(S_ / QT_, BH_), blk, ATT_SMEM>>>();
    out_gemm<<<dim3(M_ / 128, D_ / 128), blk>>>(Wo, bo, out);
}

// round 11
// speedup vs baseline: 1.1626x; 1.1626x over previous
#include <cuda_runtime.h>
#include <cuda_bf16.h>
#include <cstdint>

// Problem constants
#define B_   2
#define S_   4096
#define D_   512
#define H_   8
#define DK_  64
#define BH_  (B_*H_)
#define M_   (B_*S_)   // 8192 rows

// score scale folded into Q: 1/sqrt(64) * log2(e)  (softmax done in exp2 domain)
#define QSCALE (0.125f * 1.44269504088896341f)

// ---------------- scratch (no allocations allowed -> device globals) ----------
__device__ float g_Qh[BH_ * S_ * DK_];   // [bh][s][dk]  16 MiB
__device__ float g_Kh[BH_ * S_ * DK_];
__device__ float g_Vh[BH_ * S_ * DK_];
__device__ float g_cmax[BH_ * S_];       // per-column (k) max over q (log2 domain)
__device__ float g_csum[BH_ * S_];       // per-column (k) sum of exp2
__device__ float g_attn[M_ * D_];        // [b*S+s][h*64+dv]

// ---------------- tf32 helpers (attention core) -------------------------------
__device__ __forceinline__ float to_tf32(float x) {
    uint32_t u;
    asm("cvt.rna.tf32.f32 %0, %1;" : "=r"(u) : "f"(x));
    return __uint_as_float(u);
}

// D += A(16x8,row) * B(8x8,col)  tf32, fp32 accum
__device__ __forceinline__ void mma8(float* c,
                                     uint32_t a0, uint32_t a1, uint32_t a2, uint32_t a3,
                                     uint32_t b0, uint32_t b1) {
    asm volatile(
        "mma.sync.aligned.m16n8k8.row.col.f32.tf32.tf32.f32 "
        "{%0,%1,%2,%3}, {%4,%5,%6,%7}, {%8,%9}, {%0,%1,%2,%3};\n"
        : "+f"(c[0]), "+f"(c[1]), "+f"(c[2]), "+f"(c[3])
        : "r"(a0), "r"(a1), "r"(a2), "r"(a3), "r"(b0), "r"(b1));
}

// ---------------- cp.async helpers --------------------------------------------
__device__ __forceinline__ void cp_async16(void* smem, const void* g) {
    uint32_t s = (uint32_t)__cvta_generic_to_shared(smem);
    asm volatile("cp.async.cg.shared.global [%0], [%1], 16;\n" :: "r"(s), "l"(g));
}
#define CP_COMMIT() asm volatile("cp.async.commit_group;\n" ::: "memory")
#define CP_WAIT0()  asm volatile("cp.async.wait_group 0;\n" ::: "memory")

// ---------------- bf16 helpers (dense GEMMs, split precision) -----------------
// D += A(16x16,row) * B(16x8,col)  bf16, fp32 accum
__device__ __forceinline__ void mma16(float* c,
                                      uint32_t a0, uint32_t a1, uint32_t a2, uint32_t a3,
                                      uint32_t b0, uint32_t b1) {
    asm volatile(
        "mma.sync.aligned.m16n8k16.row.col.f32.bf16.bf16.f32 "
        "{%0,%1,%2,%3}, {%4,%5,%6,%7}, {%8,%9}, {%0,%1,%2,%3};\n"
        : "+f"(c[0]), "+f"(c[1]), "+f"(c[2]), "+f"(c[3])
        : "r"(a0), "r"(a1), "r"(a2), "r"(a3), "r"(b0), "r"(b1));
}

__device__ __forceinline__ uint32_t pack_bf2(__nv_bfloat16 lo, __nv_bfloat16 hi) {
    __nv_bfloat162 t(lo, hi);               // .x = lo (low 16 bits)
    return *reinterpret_cast<uint32_t*>(&t);
}

// split x into big(bf16) + small(bf16 of residual)
__device__ __forceinline__ void split_bf16(float x, __nv_bfloat16& b, __nv_bfloat16& s) {
    b = __float2bfloat16_rn(x);
    s = __float2bfloat16_rn(x - __bfloat162float(b));
}

// =============================================================================
// Dense GEMM core (bf16 split, 3-mma) — unchanged from round 6 (passed).
// =============================================================================
#define GEMM_BODY(A_EXPR, W_EXPR)                                                \
    __shared__ uint32_t AuB[128 * 12], AuS[128 * 12];                            \
    __shared__ uint32_t BuB[128 * 12], BuS[128 * 12];                            \
    const int tid = threadIdx.x;                                                 \
    const int warp = tid >> 5, lane = tid & 31;                                  \
    const int gid = lane >> 2, tig = lane & 3;                                   \
    const int m0w = (warp & 3) * 32;                                             \
    const int n0w = (warp >> 2) * 64;                                            \
    const int m0 = blockIdx.x * 128;                                             \
    const int n0 = blockIdx.y * 128;                                             \
    float c[2][8][4];                                                            \
    _Pragma("unroll") for (int mb = 0; mb < 2; mb++)                             \
    _Pragma("unroll") for (int nb = 0; nb < 8; nb++)                             \
    _Pragma("unroll") for (int j = 0; j < 4; j++) c[mb][nb][j] = 0.f;            \
    const int ar = tid >> 1;                                                     \
    const int ac = (tid & 1) * 8;                                                \
    const int kp = tid >> 5;                                                     \
    const int ln = tid & 31;                                                     \
    float4 pA0, pA1;                                                             \
    float pBv[8];                                                                \
    {                                                                            \
        const float* ap = &(A_EXPR)[(size_t)(m0 + ar) * D_ + ac];                \
        pA0 = *(const float4*)ap; pA1 = *(const float4*)(ap + 4);                \
        _Pragma("unroll") for (int p = 0; p < 4; p++) {                          \
            int n = ln + p * 32;                                                 \
            pBv[2*p]   = (W_EXPR)[(size_t)(2*kp    ) * D_ + n0 + n];             \
            pBv[2*p+1] = (W_EXPR)[(size_t)(2*kp + 1) * D_ + n0 + n];             \
        }                                                                        \
    }                                                                            \
    for (int kc = 0; kc < 512; kc += 16) {                                       \
        __syncthreads();                                                         \
        {                                                                        \
            __nv_bfloat16 b0,s0,b1,s1,b2,s2,b3,s3;                               \
            split_bf16(pA0.x,b0,s0); split_bf16(pA0.y,b1,s1);                    \
            split_bf16(pA0.z,b2,s2); split_bf16(pA0.w,b3,s3);                    \
            AuB[ar*12 + ac/2 + 0] = pack_bf2(b0,b1);                             \
            AuS[ar*12 + ac/2 + 0] = pack_bf2(s0,s1);                             \
            AuB[ar*12 + ac/2 + 1] = pack_bf2(b2,b3);                             \
            AuS[ar*12 + ac/2 + 1] = pack_bf2(s2,s3);                             \
            split_bf16(pA1.x,b0,s0); split_bf16(pA1.y,b1,s1);                    \
            split_bf16(pA1.z,b2,s2); split_bf16(pA1.w,b3,s3);                    \
            AuB[ar*12 + ac/2 + 2] = pack_bf2(b0,b1);                             \
            AuS[ar*12 + ac/2 + 2] = pack_bf2(s0,s1);                             \
            AuB[ar*12 + ac/2 + 3] = pack_bf2(b2,b3);                             \
            AuS[ar*12 + ac/2 + 3] = pack_bf2(s2,s3);                             \
        }                                                                        \
        {                                                                        \
            _Pragma("unroll") for (int p = 0; p < 4; p++) {                      \
                int n = ln + p * 32;                                             \
                __nv_bfloat16 xb0,xs0,xb1,xs1;                                   \
                split_bf16(pBv[2*p],xb0,xs0); split_bf16(pBv[2*p+1],xb1,xs1);    \
                BuB[n*12 + kp] = pack_bf2(xb0,xb1);                              \
                BuS[n*12 + kp] = pack_bf2(xs0,xs1);                              \
            }                                                                    \
        }                                                                        \
        if (kc + 16 < 512) {                                                     \
            const float* ap = &(A_EXPR)[(size_t)(m0 + ar) * D_ + kc + 16 + ac];  \
            pA0 = *(const float4*)ap; pA1 = *(const float4*)(ap + 4);            \
            _Pragma("unroll") for (int p = 0; p < 4; p++) {                      \
                int n = ln + p * 32;                                             \
                pBv[2*p]   = (W_EXPR)[(size_t)(kc + 16 + 2*kp    ) * D_ + n0 + n]; \
                pBv[2*p+1] = (W_EXPR)[(size_t)(kc + 16 + 2*kp + 1) * D_ + n0 + n]; \
            }                                                                    \
        }                                                                        \
        __syncthreads();                                                         \
        uint32_t a_b[2][4], a_s[2][4];                                           \
        _Pragma("unroll") for (int mb = 0; mb < 2; mb++) {                       \
            int base = (m0w + mb * 16) * 12;                                     \
            a_b[mb][0] = AuB[base + gid*12 + tig];                               \
            a_b[mb][1] = AuB[base + (gid+8)*12 + tig];                           \
            a_b[mb][2] = AuB[base + gid*12 + tig + 4];                           \
            a_b[mb][3] = AuB[base + (gid+8)*12 + tig + 4];                       \
            a_s[mb][0] = AuS[base + gid*12 + tig];                               \
            a_s[mb][1] = AuS[base + (gid+8)*12 + tig];                           \
            a_s[mb][2] = AuS[base + gid*12 + tig + 4];                           \
            a_s[mb][3] = AuS[base + (gid+8)*12 + tig + 4];                       \
        }                                                                        \
        _Pragma("unroll") for (int nb = 0; nb < 8; nb++) {                       \
            int br = (n0w + nb * 8 + gid) * 12;                                  \
            uint32_t bb0 = BuB[br + tig], bb1 = BuB[br + tig + 4];               \
            uint32_t bs0 = BuS[br + tig], bs1 = BuS[br + tig + 4];               \
            _Pragma("unroll") for (int mb = 0; mb < 2; mb++) {                   \
                mma16(c[mb][nb], a_b[mb][0],a_b[mb][1],a_b[mb][2],a_b[mb][3], bs0,bs1); \
                mma16(c[mb][nb], a_s[mb][0],a_s[mb][1],a_s[mb][2],a_s[mb][3], bb0,bb1); \
                mma16(c[mb][nb], a_b[mb][0],a_b[mb][1],a_b[mb][2],a_b[mb][3], bb0,bb1); \
            }                                                                    \
        }                                                                        \
    }

// ---- fused QKV projections: blockIdx.z selects {q,k,v} -----------------------
struct QKVArgs {
    const float* A[3];
    const float* W[3];
    const float* bias[3];
    float*       out[3];
};

__global__ __launch_bounds__(256) void qkv_gemm(QKVArgs args)
{
    const float* Ain  = args.A[blockIdx.z];
    const float* W    = args.W[blockIdx.z];
    const float* bias = args.bias[blockIdx.z];
    float*       outp = args.out[blockIdx.z];

    GEMM_BODY(Ain, W)

    const int b = m0 >> 12;            // / S_ (128 | 4096 -> one batch per tile)
#pragma unroll
    for (int mb = 0; mb < 2; mb++)
#pragma unroll
        for (int nb = 0; nb < 8; nb++) {
            int row = m0 + m0w + mb * 16 + gid;
            int s = row - b * S_;
            int ng = n0 + n0w + nb * 8 + tig * 2;
            int h = ng >> 6, dk = ng & 63;
            float bx = bias[ng], by = bias[ng + 1];
            float* dst = &outp[((size_t)(b * H_ + h) * S_ + s) * 64 + dk];
            *(float2*)dst = make_float2(c[mb][nb][0] + bx, c[mb][nb][1] + by);
            *(float2*)(dst + 8 * 64) = make_float2(c[mb][nb][2] + bx, c[mb][nb][3] + by);
        }
}

// GEMM 4: final projection g_attn[M,512] @ Wo + bo -> d_out
__global__ __launch_bounds__(256) void out_gemm(const float* __restrict__ W,
                                                const float* __restrict__ bias,
                                                float* __restrict__ out)
{
    GEMM_BODY(g_attn, W)
#pragma unroll
    for (int mb = 0; mb < 2; mb++)
#pragma unroll
        for (int nb = 0; nb < 8; nb++) {
            int row = m0 + m0w + mb * 16 + gid;
            int ng = n0 + n0w + nb * 8 + tig * 2;
            float bx = bias[ng], by = bias[ng + 1];
            *(float2*)&out[(size_t)row * D_ + ng] =
                make_float2(c[mb][nb][0] + bx, c[mb][nb][1] + by);
            *(float2*)&out[(size_t)(row + 8) * D_ + ng] =
                make_float2(c[mb][nb][2] + bx, c[mb][nb][3] + by);
        }
}

// =============================================================================
// Kernel 2 (tf32 mma, v2): column stats.  Block = 128-k tile, 8 warps each
// owning a disjoint 16-k strip with K fragments REGISTER-RESIDENT.  Q streamed
// through smem (prefetched).  Running m/Z per k-row kept in registers with
// quad-shfl reductions — no smem reduction phases, 2 barriers per q-tile.
// A = K (m-dim = k rows), B = Q (n-dim = q cols); c[row=k][col=q].
// =============================================================================
__global__ __launch_bounds__(256) void stats_kernel()
{
    __shared__ float Qt[64][68];   // [q][d]

    const int tid = threadIdx.x;
    const int warp = tid >> 5, lane = tid & 31;
    const int gid = lane >> 2, tig = lane & 3;
    const int k0w = warp * 16;

    const int bh = blockIdx.y;
    const int k0 = blockIdx.x * 128;
    const float* Kb = g_Kh + (size_t)bh * S_ * DK_;
    const float* Qb = g_Qh + (size_t)bh * S_ * DK_;

    // K fragments register-resident (rna tf32), rows k0w+gid / k0w+gid+8
    uint32_t ka[8][4];
    {
        const float* kr0 = Kb + (size_t)(k0 + k0w + gid) * DK_;
        const float* kr8 = kr0 + 8 * DK_;
#pragma unroll
        for (int kk8 = 0; kk8 < 8; kk8++) {
            int d0 = kk8 * 8;
            ka[kk8][0] = __float_as_uint(to_tf32(kr0[d0 + tig]));
            ka[kk8][1] = __float_as_uint(to_tf32(kr8[d0 + tig]));
            ka[kk8][2] = __float_as_uint(to_tf32(kr0[d0 + tig + 4]));
            ka[kk8][3] = __float_as_uint(to_tf32(kr8[d0 + tig + 4]));
        }
    }

    float m0r = -1e30f, m1r = -1e30f, z0r = 0.f, z1r = 0.f;

    const int lr = tid >> 2;           // q row 0..63
    const int lcb = (tid & 3) * 16;    // d base

    // prefetch first Q tile
    float4 pQ[4];
#pragma unroll
    for (int u = 0; u < 4; u++)
        pQ[u] = *(const float4*)&Qb[(size_t)lr * DK_ + lcb + u * 4];

    for (int q0 = 0; q0 < S_; q0 += 64) {
        __syncthreads();
#pragma unroll
        for (int u = 0; u < 4; u++) {
            float4 o;
            o.x = to_tf32(pQ[u].x * QSCALE); o.y = to_tf32(pQ[u].y * QSCALE);
            o.z = to_tf32(pQ[u].z * QSCALE); o.w = to_tf32(pQ[u].w * QSCALE);
            *(float4*)&Qt[lr][lcb + u * 4] = o;
        }
        if (q0 + 64 < S_) {
#pragma unroll
            for (int u = 0; u < 4; u++)
                pQ[u] = *(const float4*)&Qb[(size_t)(q0 + 64 + lr) * DK_ + lcb + u * 4];
        }
        __syncthreads();

        float sc[8][4];
#pragma unroll
        for (int nb = 0; nb < 8; nb++)
#pragma unroll
            for (int j = 0; j < 4; j++) sc[nb][j] = 0.f;

#pragma unroll
        for (int kk8 = 0; kk8 < 8; kk8++) {
            int d0 = kk8 * 8;
#pragma unroll
            for (int nb = 0; nb < 8; nb++) {
                uint32_t b0 = __float_as_uint(Qt[nb * 8 + gid][d0 + tig]);
                uint32_t b1 = __float_as_uint(Qt[nb * 8 + gid][d0 + tig + 4]);
                mma8(sc[nb], ka[kk8][0], ka[kk8][1], ka[kk8][2], ka[kk8][3], b0, b1);
            }
        }

        // per-k-row tile max over 64 q (regs + quad shfl)
        float tm0 = -1e30f, tm1 = -1e30f;
#pragma unroll
        for (int nb = 0; nb < 8; nb++) {
            tm0 = fmaxf(tm0, fmaxf(sc[nb][0], sc[nb][1]));
            tm1 = fmaxf(tm1, fmaxf(sc[nb][2], sc[nb][3]));
        }
        tm0 = fmaxf(tm0, __shfl_xor_sync(0xffffffffu, tm0, 1));
        tm0 = fmaxf(tm0, __shfl_xor_sync(0xffffffffu, tm0, 2));
        tm1 = fmaxf(tm1, __shfl_xor_sync(0xffffffffu, tm1, 1));
        tm1 = fmaxf(tm1, __shfl_xor_sync(0xffffffffu, tm1, 2));

        float mn0 = fmaxf(m0r, tm0);
        float mn1 = fmaxf(m1r, tm1);

        float ts0 = 0.f, ts1 = 0.f;
#pragma unroll
        for (int nb = 0; nb < 8; nb++) {
            ts0 += exp2f(sc[nb][0] - mn0) + exp2f(sc[nb][1] - mn0);
            ts1 += exp2f(sc[nb][2] - mn1) + exp2f(sc[nb][3] - mn1);
        }
        ts0 += __shfl_xor_sync(0xffffffffu, ts0, 1);
        ts0 += __shfl_xor_sync(0xffffffffu, ts0, 2);
        ts1 += __shfl_xor_sync(0xffffffffu, ts1, 1);
        ts1 += __shfl_xor_sync(0xffffffffu, ts1, 2);

        z0r = z0r * exp2f(m0r - mn0) + ts0;  m0r = mn0;
        z1r = z1r * exp2f(m1r - mn1) + ts1;  m1r = mn1;
    }

    if (tig == 0) {
        int kg = bh * S_ + k0 + k0w + gid;
        g_cmax[kg]     = m0r;  g_csum[kg]     = z0r;
        g_cmax[kg + 8] = m1r;  g_csum[kg + 8] = z1r;
    }
}

// =============================================================================
// Kernel 3 (tf32 mma, v2): output pass with FAT WARPS.  Block = 128 threads,
// 4 warps x 32 q rows; streams 64-k tiles: V via cp.async (raw fp32 — identical
// numerics to round 6), K rna.  Each B fragment feeds 2 mma -> smem traffic
// nearly halves.  Ps/Vs use stride 72 (== 8 mod 32) for conflict-free access.
// =============================================================================
#define QT_  128
// floats: Qt 128*68 | Kt 64*68 | Vs 64*72 | Ps 128*72 | mk 64 | zk 64
#define OFF_KT (128 * 68)
#define OFF_VS (OFF_KT + 64 * 68)
#define OFF_PS (OFF_VS + 64 * 72)
#define OFF_MK (OFF_PS + 128 * 72)
#define ATT_SMEM ((OFF_MK + 128) * 4)

__global__ __launch_bounds__(128) void attn_kernel()
{
    extern __shared__ float sm[];
    float (*Qt)[68] = (float(*)[68])(sm);            // [q][d]  128 rows
    float (*Kt)[68] = (float(*)[68])(sm + OFF_KT);   // [k][d]  64 rows
    float (*Vs)[72] = (float(*)[72])(sm + OFF_VS);   // [k][d]  64 rows (raw fp32)
    float (*Ps)[72] = (float(*)[72])(sm + OFF_PS);   // [q][k]  128 rows
    float* mk = sm + OFF_MK;
    float* zk = mk + 64;

    const int tid = threadIdx.x;
    const int warp = tid >> 5, lane = tid & 31;
    const int gid = lane >> 2, tig = lane & 3;
    const int q0w = warp * 32;          // 32 q rows per warp

    const int bh = blockIdx.y;
    const int q0 = blockIdx.x * QT_;
    const int b = bh >> 3, h = bh & 7;
    const float* Qb = g_Qh + (size_t)bh * S_ * DK_;
    const float* Kb = g_Kh + (size_t)bh * S_ * DK_;
    const float* Vb = g_Vh + (size_t)bh * S_ * DK_;

    // Q tile once: thread fills row tid (QSCALE + rna, same transform as stats)
#pragma unroll
    for (int u = 0; u < 16; u++) {
        float4 t = *(const float4*)&Qb[(size_t)(q0 + tid) * DK_ + u * 4];
        float4 o;
        o.x = to_tf32(t.x * QSCALE); o.y = to_tf32(t.y * QSCALE);
        o.z = to_tf32(t.z * QSCALE); o.w = to_tf32(t.w * QSCALE);
        *(float4*)&Qt[tid][u * 4] = o;
    }

    float acc[2][8][4];
#pragma unroll
    for (int mb = 0; mb < 2; mb++)
#pragma unroll
        for (int nb = 0; nb < 8; nb++)
#pragma unroll
            for (int j = 0; j < 4; j++) acc[mb][nb][j] = 0.f;

    const int vr = tid >> 1;            // k row 0..63
    const int vc = (tid & 1) * 32;      // d half

    for (int k0 = 0; k0 < S_; k0 += 64) {
        __syncthreads();   // previous tile's Kt/Vs/Ps/mk/zk free

        // V: cp.async raw fp32 (mma truncates — same as round 6)
#pragma unroll
        for (int u = 0; u < 8; u++)
            cp_async16(&Vs[vr][vc + u * 4], &Vb[(size_t)(k0 + vr) * DK_ + vc + u * 4]);
        CP_COMMIT();

        // K: LDG + rna + STS
#pragma unroll
        for (int u = 0; u < 8; u++) {
            float4 t = *(const float4*)&Kb[(size_t)(k0 + vr) * DK_ + vc + u * 4];
            float4 o;
            o.x = to_tf32(t.x); o.y = to_tf32(t.y);
            o.z = to_tf32(t.z); o.w = to_tf32(t.w);
            *(float4*)&Kt[vr][vc + u * 4] = o;
        }
        if (tid < 64) {
            mk[tid] = g_cmax[bh * S_ + k0 + tid];
            zk[tid] = 1.f / g_csum[bh * S_ + k0 + tid];
        }
        CP_WAIT0();
        __syncthreads();

        // ---- scores: 32q x 64k per warp
        float sc[2][8][4];
#pragma unroll
        for (int mb = 0; mb < 2; mb++)
#pragma unroll
            for (int nb = 0; nb < 8; nb++)
#pragma unroll
                for (int j = 0; j < 4; j++) sc[mb][nb][j] = 0.f;

#pragma unroll
        for (int kk = 0; kk < 64; kk += 8) {
            uint32_t a[2][4];
#pragma unroll
            for (int mb = 0; mb < 2; mb++) {
                int r = q0w + mb * 16;
                a[mb][0] = __float_as_uint(Qt[r + gid][kk + tig]);
                a[mb][1] = __float_as_uint(Qt[r + gid + 8][kk + tig]);
                a[mb][2] = __float_as_uint(Qt[r + gid][kk + tig + 4]);
                a[mb][3] = __float_as_uint(Qt[r + gid + 8][kk + tig + 4]);
            }
#pragma unroll
            for (int nb = 0; nb < 8; nb++) {
                uint32_t b0 = __float_as_uint(Kt[nb * 8 + gid][kk + tig]);
                uint32_t b1 = __float_as_uint(Kt[nb * 8 + gid][kk + tig + 4]);
                mma8(sc[0][nb], a[0][0], a[0][1], a[0][2], a[0][3], b0, b1);
                mma8(sc[1][nb], a[1][0], a[1][1], a[1][2], a[1][3], b0, b1);
            }
        }

        // ---- p = exp2(s - m_k) / Z_k, write warp-private P tile
#pragma unroll
        for (int mb = 0; mb < 2; mb++) {
            int r = q0w + mb * 16;
#pragma unroll
            for (int nb = 0; nb < 8; nb++) {
                int col = nb * 8 + tig * 2;
                float m0 = mk[col], z0 = zk[col];
                float m1 = mk[col + 1], z1 = zk[col + 1];
                float p0 = exp2f(sc[mb][nb][0] - m0) * z0;
                float p1 = exp2f(sc[mb][nb][1] - m1) * z1;
                float p2 = exp2f(sc[mb][nb][2] - m0) * z0;
                float p3 = exp2f(sc[mb][nb][3] - m1) * z1;
                *(float2*)&Ps[r + gid][col]     = make_float2(p0, p1);
                *(float2*)&Ps[r + gid + 8][col] = make_float2(p2, p3);
            }
        }
        __syncwarp();   // Ps rows [q0w, q0w+32) are produced+consumed by this warp

        // ---- acc += P @ V   (A from Ps[q][k], B from Vs[k][d])
#pragma unroll
        for (int kk = 0; kk < 64; kk += 8) {
            uint32_t a[2][4];
#pragma unroll
            for (int mb = 0; mb < 2; mb++) {
                int r = q0w + mb * 16;
                a[mb][0] = __float_as_uint(Ps[r + gid][kk + tig]);
                a[mb][1] = __float_as_uint(Ps[r + gid + 8][kk + tig]);
                a[mb][2] = __float_as_uint(Ps[r + gid][kk + tig + 4]);
                a[mb][3] = __float_as_uint(Ps[r + gid + 8][kk + tig + 4]);
            }
#pragma unroll
            for (int nb = 0; nb < 8; nb++) {
                uint32_t b0 = __float_as_uint(Vs[kk + tig][nb * 8 + gid]);
                uint32_t b1 = __float_as_uint(Vs[kk + tig + 4][nb * 8 + gid]);
                mma8(acc[0][nb], a[0][0], a[0][1], a[0][2], a[0][3], b0, b1);
                mma8(acc[1][nb], a[1][0], a[1][1], a[1][2], a[1][3], b0, b1);
            }
        }
    }

    // epilogue: scatter to [b*S+q][h*64+d]
#pragma unroll
    for (int mb = 0; mb < 2; mb++)
#pragma unroll
        for (int nb = 0; nb < 8; nb++) {
            int col = nb * 8 + tig * 2;
            int q = q0 + q0w + mb * 16 + gid;
            *(float2*)&g_attn[((size_t)b * S_ + q) * D_ + h * 64 + col] =
                make_float2(acc[mb][nb][0], acc[mb][nb][1]);
            *(float2*)&g_attn[((size_t)b * S_ + q + 8) * D_ + h * 64 + col] =
                make_float2(acc[mb][nb][2], acc[mb][nb][3]);
        }
}

// =============================================================================
extern "C" void kernel_launch(void* const* d_in, const int* in_sizes, int n_in,
                              void* d_out, int out_size)
{
    const float* q  = (const float*)d_in[0];
    const float* k  = (const float*)d_in[1];
    const float* v  = (const float*)d_in[2];
    const float* Wq = (const float*)d_in[3];
    const float* bq = (const float*)d_in[4];
    const float* Wk = (const float*)d_in[5];
    const float* bk = (const float*)d_in[6];
    const float* Wv = (const float*)d_in[7];
    const float* bv = (const float*)d_in[8];
    const float* Wo = (const float*)d_in[9];
    const float* bo = (const float*)d_in[10];
    float* out = (float*)d_out;

    cudaFuncSetAttribute(attn_kernel, cudaFuncAttributeMaxDynamicSharedMemorySize,
                         ATT_SMEM);

    float* Qh;  cudaGetSymbolAddress((void**)&Qh, g_Qh);
    float* Kh;  cudaGetSymbolAddress((void**)&Kh, g_Kh);
    float* Vh;  cudaGetSymbolAddress((void**)&Vh, g_Vh);

    QKVArgs qa;
    qa.A[0] = q;  qa.A[1] = k;  qa.A[2] = v;
    qa.W[0] = Wq; qa.W[1] = Wk; qa.W[2] = Wv;
    qa.bias[0] = bq; qa.bias[1] = bk; qa.bias[2] = bv;
    qa.out[0] = Qh; qa.out[1] = Kh; qa.out[2] = Vh;

    qkv_gemm<<<dim3(M_ / 128, D_ / 128, 3), dim3(256)>>>(qa);
    stats_kernel<<<dim3(S_ / 128, BH_), dim3(256)>>>();
    attn_kernel<<<dim3(S_ / QT_, BH_), dim3(128), ATT_SMEM>>>();
    out_gemm<<<dim3(M_ / 128, D_ / 128), dim3(256)>>>(Wo, bo, out);
}